// round 15
// baseline (speedup 1.0000x reference)
#include <cuda_runtime.h>

// Shapes (fixed)
#define Bn 16
#define In 32
#define Cn 8
#define Jn 10
#define Dn 16
#define Xn 576    // D*H*W (one CTA owns a full (b,j) slice)
#define NT 288    // threads; each owns x and x+288
#define HWn 36
#define EPSf 1e-7f
#define GRID2 (Bn*Jn)   // 160 CTAs, 2/SM co-resident (113-reg budget)

// Cross-CTA comm scratch, parity double-buffered (WAR-safe with one grid
// barrier per iteration; validated R9).
__device__ float    g_nPart[2][GRID2];        // [b*Jn + j]
__device__ float    g_aPart[2][GRID2 * In];   // [entry][i], 128B coalesced rows
__device__ unsigned g_leaf[Bn];               // hierarchical barrier leaves (monotonic)
__device__ unsigned g_root;                   // root counter (monotonic)
__device__ unsigned g_gen;                    // generation (monotonic)

__device__ __forceinline__ float squash_k(float n) {
    float n2 = n * n;
    return (n2 / (1.f + n2)) / (n + EPSf);
}

// Hierarchical grid barrier: 10 arrivals per leaf (one batch), 16 leaves ->
// root -> gen bump. Monotonic counters (no reset race, graph-replay safe).
__device__ __forceinline__ void gridBarrier(int b) {
    __threadfence();
    __syncthreads();
    if (threadIdx.x == 0) {
        unsigned g0 = *(volatile unsigned*)&g_gen;   // capture BEFORE arriving
        unsigned l = atomicAdd(&g_leaf[b], 1u);
        if ((l + 1u) % Jn == 0u) {                   // last of this batch's 10
            unsigned r = atomicAdd(&g_root, 1u);
            if ((r + 1u) % Bn == 0u) {               // last leaf
                __threadfence();
                atomicAdd(&g_gen, 1u);
            }
        }
        while (*(volatile unsigned*)&g_gen == g0) __nanosleep(64);
        __threadfence();
    }
    __syncthreads();
}

// Block sum over 288 threads (9 warps); valid on thread 0.
__device__ __forceinline__ float blockReduceSum288(float v) {
    __shared__ float red[9];
    int lane = threadIdx.x & 31, w = threadIdx.x >> 5;
    #pragma unroll
    for (int o = 16; o > 0; o >>= 1) v += __shfl_down_sync(0xffffffffu, v, o);
    if (lane == 0) red[w] = v;
    __syncthreads();
    float s = 0.f;
    if (threadIdx.x == 0) {
        #pragma unroll
        for (int k = 0; k < 9; k++) s += red[k];
    }
    return s;
}

__global__ void __launch_bounds__(NT, 2) routing_all(
    const float* __restrict__ u, const float* __restrict__ bias,
    float* __restrict__ out)
{
    extern __shared__ __align__(16) float Us[];   // Us[i*Xn + x], 73,728 B
    __shared__ float ss[Xn];
    __shared__ float sb[In * Jn];     // routing logits (identical in all CTAs)
    __shared__ float cs[In];          // coupling coeffs for this CTA's j
    __shared__ float kb_sh;
    int bj = blockIdx.x;
    int b = bj / Jn, j = bj % Jn;
    int x = threadIdx.x;
    int w = x >> 5, lane = x & 31;
    float bias0 = bias[j * Dn + x / HWn];
    float bias1 = bias[j * Dn + (x + NT) / HWn];

    for (int t = x; t < In * Jn; t += NT) sb[t] = 0.f;

    // ---- Load phase (R9-proven): Us[i][x] = sum_c u_hat[b,i,c,j,x].
    // 2 i-groups x 144 float4-cols, plain __ldcs, deep batching.
    float tot0, tot1;
    {
        int t4 = x % 144, g = x / 144;
        int xq = t4 * 4;
        const float* base = u + (size_t)b * In * Cn * Jn * Xn + (size_t)j * Xn + xq;
        #pragma unroll 2
        for (int ii = 0; ii < 16; ii++) {
            int i = g * 16 + ii;
            const float4* p = (const float4*)(base + (size_t)i * Cn * Jn * Xn);
            float4 a0 = __ldcs(p);
            float4 a1 = __ldcs(p + 1 * (Jn * Xn / 4));
            float4 a2 = __ldcs(p + 2 * (Jn * Xn / 4));
            float4 a3 = __ldcs(p + 3 * (Jn * Xn / 4));
            float4 a4 = __ldcs(p + 4 * (Jn * Xn / 4));
            float4 a5 = __ldcs(p + 5 * (Jn * Xn / 4));
            float4 a6 = __ldcs(p + 6 * (Jn * Xn / 4));
            float4 a7 = __ldcs(p + 7 * (Jn * Xn / 4));
            float4 acc;
            acc.x = ((a0.x + a1.x) + (a2.x + a3.x)) + ((a4.x + a5.x) + (a6.x + a7.x));
            acc.y = ((a0.y + a1.y) + (a2.y + a3.y)) + ((a4.y + a5.y) + (a6.y + a7.y));
            acc.z = ((a0.z + a1.z) + (a2.z + a3.z)) + ((a4.z + a5.z) + (a6.z + a7.z));
            acc.w = ((a0.w + a1.w) + (a2.w + a3.w)) + ((a4.w + a5.w) + (a6.w + a7.w));
            *(float4*)&Us[i * Xn + xq] = acc;
        }
        __syncthreads();
        tot0 = 0.f; tot1 = 0.f;
        #pragma unroll
        for (int i = 0; i < In; i++) {
            tot0 += Us[i * Xn + x];
            tot1 += Us[i * Xn + x + NT];
        }
    }

    float s0 = 0.f, s1 = 0.f;
    #pragma unroll 1
    for (int iter = 0; iter < 3; iter++) {
        int pb = iter & 1;

        // ---- routing update (iter > 0): warp-redundant kb, coalesced
        // agreement reads (lane = i), no intermediate __syncthreads.
        if (iter > 0) {
            int prev = (iter - 1) & 1;
            // each warp computes all 16 kb in-lane
            float kb_l = 0.f;
            if (lane < Bn) {
                float nn = 0.f;
                #pragma unroll
                for (int t = 0; t < Jn; t++) nn += __ldcg(&g_nPart[prev][lane * Jn + t]);
                kb_l = squash_k(nn);
            }
            for (int jj = w; jj < Jn; jj += 9) {
                float a = 0.f;
                #pragma unroll
                for (int bb = 0; bb < Bn; bb++) {
                    float kb = __shfl_sync(0xffffffffu, kb_l, bb);
                    int ent = bb * Jn + jj;
                    a += kb * __ldcg(&g_aPart[prev][(size_t)ent * In + lane]);
                }
                sb[lane * Jn + jj] += a;     // b_ij += agreement
            }
            __syncthreads();
            if (x < In) {
                float mx = -1e30f;
                #pragma unroll
                for (int jj = 0; jj < Jn; jj++) mx = fmaxf(mx, sb[x * Jn + jj]);
                float den = 0.f;
                #pragma unroll
                for (int jj = 0; jj < Jn; jj++) den += __expf(sb[x * Jn + jj] - mx);
                cs[x] = __expf(sb[x * Jn + j] - mx) / den;
            }
            __syncthreads();
        }

        // ---- s_j: thread owns x and x+288
        if (iter == 0) {
            s0 = tot0 * (1.0f / Jn) + bias0;   // softmax(0) = 1/J exactly
            s1 = tot1 * (1.0f / Jn) + bias1;
        } else {
            float a0 = 0.f, a1 = 0.f;
            #pragma unroll
            for (int i = 0; i < In; i++) {
                float c = cs[i];
                a0 += c * Us[i * Xn + x];
                a1 += c * Us[i * Xn + x + NT];
            }
            s0 = a0 + bias0;
            s1 = a1 + bias1;
        }
        float n = blockReduceSum288(fabsf(s0) + fabsf(s1));
        if (x == 0) g_nPart[pb][bj] = n;

        if (iter == 2) break;                  // final agreement is dead

        ss[x] = s0;
        ss[x + NT] = s1;
        __syncthreads();
        if (w < 8) {
            #pragma unroll
            for (int ii = 0; ii < 4; ii++) {
                int i = w * 4 + ii;
                float a = 0.f;
                #pragma unroll
                for (int xx = lane; xx < Xn; xx += 32) a += Us[i * Xn + xx] * ss[xx];
                #pragma unroll
                for (int o = 16; o > 0; o >>= 1) a += __shfl_down_sync(0xffffffffu, a, o);
                if (lane == 0) g_aPart[pb][(size_t)bj * In + i] = a;
            }
        }
        gridBarrier(b);
    }

    // ---- final squash (iter-2 norms in buffer 0)
    gridBarrier(b);
    if (x < 32) {
        float v = (lane < Jn) ? __ldcg(&g_nPart[0][b * Jn + lane]) : 0.f;
        #pragma unroll
        for (int o = 16; o > 0; o >>= 1) v += __shfl_down_sync(0xffffffffu, v, o);
        if (lane == 0) kb_sh = squash_k(v);
    }
    __syncthreads();
    float kb = kb_sh;
    out[(size_t)bj * Xn + x]      = kb * s0;
    out[(size_t)bj * Xn + x + NT] = kb * s1;
}

extern "C" void kernel_launch(void* const* d_in, const int* in_sizes, int n_in,
                              void* d_out, int out_size) {
    const float* u    = (const float*)d_in[0];
    const float* bias = (const float*)d_in[1];
    float* out = (float*)d_out;
    const int dyn_smem = In * Xn * sizeof(float);   // 73,728 B
    cudaFuncSetAttribute(routing_all,
                         cudaFuncAttributeMaxDynamicSharedMemorySize, dyn_smem);
    routing_all<<<GRID2, NT, dyn_smem>>>(u, bias, out);
}

// round 16
// speedup vs baseline: 1.6495x; 1.6495x over previous
#include <cuda_runtime.h>

// Shapes (fixed)
#define Bn 16
#define In 32
#define Cn 8
#define Jn 10
#define Dn 16
#define Xn 576   // D*H*W (one CTA owns a full (b,j) slice)
#define NT 288   // threads per CTA; each owns x and x+288
#define HWn 36
#define EPSf 1e-7f
#define GRID2 (Bn*Jn)   // 160 CTAs -> co-residency needs only 2 CTAs/SM

// Cross-CTA comm scratch, parity double-buffered (WAR safety across the single
// per-iteration grid barrier). Exactly R9's layout.
__device__ float    g_nPart[2][GRID2];         // per-(b,j) L1-norm of s
__device__ float    g_aPart[2][GRID2 * In];    // [entry][i], i contiguous (128B rows)
__device__ unsigned g_cnt;
__device__ unsigned g_gen;

__device__ __forceinline__ float squash_k(float n) {
    float n2 = n * n;
    return (n2 / (1.f + n2)) / (n + EPSf);
}

// Flat grid barrier (R9-validated). 160 CTAs co-resident (160 <= 148*2).
__device__ __forceinline__ void gridBarrier() {
    __threadfence();
    __syncthreads();
    if (threadIdx.x == 0) {
        unsigned g0 = *(volatile unsigned*)&g_gen;
        unsigned a = atomicAdd(&g_cnt, 1u);
        if (a == GRID2 - 1) {
            atomicExch(&g_cnt, 0u);
            __threadfence();
            atomicAdd(&g_gen, 1u);
        } else {
            while (*(volatile unsigned*)&g_gen == g0) { }
        }
        __threadfence();
    }
    __syncthreads();
}

// Block sum over 288 threads; valid on thread 0.
__device__ __forceinline__ float blockReduceSum288(float v) {
    __shared__ float red[9];
    int lane = threadIdx.x & 31, w = threadIdx.x >> 5;
    #pragma unroll
    for (int o = 16; o > 0; o >>= 1) v += __shfl_down_sync(0xffffffffu, v, o);
    if (lane == 0) red[w] = v;
    __syncthreads();
    float s = 0.f;
    if (threadIdx.x == 0) {
        #pragma unroll
        for (int k = 0; k < 9; k++) s += red[k];
    }
    return s;
}

__global__ void __launch_bounds__(NT, 2) routing_all(
    const float* __restrict__ u, const float* __restrict__ bias,
    float* __restrict__ out)
{
    // U tile for the full (b,j) slice: 32 x 576 floats = 73,728 B (dynamic smem)
    extern __shared__ __align__(16) float Us[];   // Us[i*Xn + x]
    __shared__ float ss[Xn];
    __shared__ float sb[In * Jn];     // routing logits (identical in all CTAs)
    __shared__ float cs[In];          // coupling coeffs for this CTA's j
    __shared__ float kb_sh[Bn];
    int bj = blockIdx.x;
    int b = bj / Jn, j = bj % Jn;
    int x = threadIdx.x;
    int w = x >> 5, lane = x & 31;
    float bias0 = bias[j * Dn + x / HWn];
    float bias1 = bias[j * Dn + (x + NT) / HWn];

    for (int t = x; t < In * Jn; t += NT) sb[t] = 0.f;

    // ---- Load phase: Us[i][x] = sum_c u_hat[b,i,c,j,x]. 94 MB streamed once.
    // 2 i-groups x 144 float4-cols (R9-exact).
    {
        int t4 = x % 144, g = x / 144;        // g in {0,1}, 16 i's each
        int xq = t4 * 4;
        const float* base = u + (size_t)b * In * Cn * Jn * Xn + (size_t)j * Xn + xq;
        #pragma unroll 2
        for (int ii = 0; ii < 16; ii++) {
            int i = g * 16 + ii;
            const float4* p = (const float4*)(base + (size_t)i * Cn * Jn * Xn);
            float4 a0 = __ldcs(p);
            float4 a1 = __ldcs(p + 1 * (Jn * Xn / 4));
            float4 a2 = __ldcs(p + 2 * (Jn * Xn / 4));
            float4 a3 = __ldcs(p + 3 * (Jn * Xn / 4));
            float4 a4 = __ldcs(p + 4 * (Jn * Xn / 4));
            float4 a5 = __ldcs(p + 5 * (Jn * Xn / 4));
            float4 a6 = __ldcs(p + 6 * (Jn * Xn / 4));
            float4 a7 = __ldcs(p + 7 * (Jn * Xn / 4));
            float4 acc;
            acc.x = ((a0.x + a1.x) + (a2.x + a3.x)) + ((a4.x + a5.x) + (a6.x + a7.x));
            acc.y = ((a0.y + a1.y) + (a2.y + a3.y)) + ((a4.y + a5.y) + (a6.y + a7.y));
            acc.z = ((a0.z + a1.z) + (a2.z + a3.z)) + ((a4.z + a5.z) + (a6.z + a7.z));
            acc.w = ((a0.w + a1.w) + (a2.w + a3.w)) + ((a4.w + a5.w) + (a6.w + a7.w));
            *(float4*)&Us[i * Xn + xq] = acc;
        }
    }
    __syncthreads();

    float s0 = 0.f, s1 = 0.f;
    #pragma unroll 1
    for (int iter = 0; iter < 3; iter++) {
        int pb = iter & 1;

        // ---- routing update from previous iteration's partials (iter > 0).
        // Coalesced: lane = i, each g_aPart entry row is one 128B line. (R9-exact)
        if (iter > 0) {
            int prev = (iter - 1) & 1;
            if (x < Bn) {
                float nn = 0.f;
                #pragma unroll
                for (int t = 0; t < Jn; t++) nn += __ldcg(&g_nPart[prev][x * Jn + t]);
                kb_sh[x] = squash_k(nn);
            }
            __syncthreads();
            for (int jj = w; jj < Jn; jj += 9) {
                float a = 0.f;
                #pragma unroll
                for (int bb = 0; bb < Bn; bb++) {
                    int ent = bb * Jn + jj;
                    a += kb_sh[bb] * __ldcg(&g_aPart[prev][(size_t)ent * In + lane]);
                }
                sb[lane * Jn + jj] += a;      // b_ij += agreement
            }
            __syncthreads();
            if (x < In) {
                float mx = -1e30f;
                #pragma unroll
                for (int jj = 0; jj < Jn; jj++) mx = fmaxf(mx, sb[x * Jn + jj]);
                float den = 0.f;
                #pragma unroll
                for (int jj = 0; jj < Jn; jj++) den += __expf(sb[x * Jn + jj] - mx);
                cs[x] = __expf(sb[x * Jn + j] - mx) / den;
            }
            __syncthreads();
        }

        // ---- s_j for this (b,j): thread owns x and x+288
        if (iter == 0) {
            float a0 = 0.f, a1 = 0.f;
            #pragma unroll
            for (int i = 0; i < In; i++) {
                a0 += Us[i * Xn + x];
                a1 += Us[i * Xn + x + NT];
            }
            s0 = a0 * (1.0f / Jn) + bias0;    // softmax(0) = 1/J exactly
            s1 = a1 * (1.0f / Jn) + bias1;
        } else {
            float a0 = 0.f, a1 = 0.f;
            #pragma unroll
            for (int i = 0; i < In; i++) {
                float c = cs[i];
                a0 += c * Us[i * Xn + x];
                a1 += c * Us[i * Xn + x + NT];
            }
            s0 = a0 + bias0;
            s1 = a1 + bias1;
        }
        // ---- L1-norm (full (b,j) slice in one CTA)
        float n = blockReduceSum288(fabsf(s0) + fabsf(s1));
        if (x == 0) g_nPart[pb][bj] = n;

        if (iter == 2) break;                 // final agreement is dead

        ss[x] = s0;
        ss[x + NT] = s1;
        __syncthreads();
        // ---- unscaled agreement partials: aU[i] = sum_x Us[i][x]*ss[x]
        if (w < 8) {
            #pragma unroll
            for (int ii = 0; ii < 4; ii++) {
                int i = w * 4 + ii;
                float a = 0.f;
                #pragma unroll
                for (int xx = lane; xx < Xn; xx += 32) a += Us[i * Xn + xx] * ss[xx];
                #pragma unroll
                for (int o = 16; o > 0; o >>= 1) a += __shfl_down_sync(0xffffffffu, a, o);
                if (lane == 0) g_aPart[pb][(size_t)bj * In + i] = a;
            }
        }
        gridBarrier();
    }

    // ---- final squash (iter-2 norms are in buffer 0); warp-parallel reduce
    gridBarrier();
    if (x < 32) {
        float v = (lane < Jn) ? __ldcg(&g_nPart[0][b * Jn + lane]) : 0.f;
        #pragma unroll
        for (int o = 16; o > 0; o >>= 1) v += __shfl_down_sync(0xffffffffu, v, o);
        if (lane == 0) kb_sh[0] = squash_k(v);
    }
    __syncthreads();
    float kb = kb_sh[0];
    out[(size_t)bj * Xn + x]      = kb * s0;
    out[(size_t)bj * Xn + x + NT] = kb * s1;
}

extern "C" void kernel_launch(void* const* d_in, const int* in_sizes, int n_in,
                              void* d_out, int out_size) {
    const float* u    = (const float*)d_in[0];
    const float* bias = (const float*)d_in[1];
    float* out = (float*)d_out;
    const int dyn_smem = In * Xn * sizeof(float);   // 73,728 B
    cudaFuncSetAttribute(routing_all,
                         cudaFuncAttributeMaxDynamicSharedMemorySize, dyn_smem);
    routing_all<<<GRID2, NT, dyn_smem>>>(u, bias, out);
}